// round 16
// baseline (speedup 1.0000x reference)
#include <cuda_runtime.h>
#include <cuda_fp16.h>
#include <math.h>

// Fixed problem shapes
#define Bb 8
#define Cc 256
#define Hf 48
#define Wf 48
#define RR 300
#define SCALE 0.0625f
#define MAXW 5          // grid pts per axis per bin: window span < 5.86 -> <= 5
#define MAXNJR 23       // max ROI window span (rows)
#define CCH 64          // channels per work item
#define RES_PITCH 67    // odd mod 32 -> conflict-free write-out gather
#define NITEMS (RR * 4) // (roi, chunk) work items

#define STAGE_HALFS  (MAXNJR * 7 * CCH)              // 10304 halves = 20608 B
#define RES_BYTES    (49 * RES_PITCH * 4)            // 13132 B (aliases stage)
#define DYN_SMEM     (STAGE_HALFS * 2)               // 20608 B

// Channels-last fp16 features: [B][H][W][C], zero pad covers fixed-5 over-reads
// (matching weights are exactly 0.0 there).
__device__ __half g_featTh[(size_t)Bb * Hf * Wf * Cc + 4096];
__device__ unsigned int g_ctr;     // work-stealing counter (reset by transpose)

// ---------------------------------------------------------------------------
// Stage 1: transpose [B][C][S] -> fp16 [B][S][C], S = H*W = 2304.
// ---------------------------------------------------------------------------
__global__ void __launch_bounds__(256) transpose_kernel(const float* __restrict__ feat) {
    __shared__ float tile[32][33];     // [c_rel][s_rel]
    const int S = Hf * Wf;
    const int b  = blockIdx.z;
    const int s0 = blockIdx.x * 32;
    const int c0 = blockIdx.y * 32;
    const int tx = threadIdx.x;        // 0..7
    const int ty = threadIdx.y;        // 0..31

    if (tx == 0 && ty == 0 && blockIdx.x == 0 && blockIdx.y == 0 && blockIdx.z == 0)
        g_ctr = 0u;                    // pool kernel launches after us (stream order)

    float4 v = *(const float4*)&feat[((size_t)b * Cc + c0 + ty) * S + s0 + 4 * tx];
    tile[ty][4 * tx + 0] = v.x;
    tile[ty][4 * tx + 1] = v.y;
    tile[ty][4 * tx + 2] = v.z;
    tile[ty][4 * tx + 3] = v.w;
    __syncthreads();

    float4 w;
    w.x = tile[4 * tx + 0][ty];
    w.y = tile[4 * tx + 1][ty];
    w.z = tile[4 * tx + 2][ty];
    w.w = tile[4 * tx + 3][ty];
    union { __half2 h[2]; uint2 u; } pk;
    pk.h[0] = __floats2half2_rn(w.x, w.y);
    pk.h[1] = __floats2half2_rn(w.z, w.w);
    *(uint2*)&g_featTh[((size_t)b * S + s0 + ty) * Cc + c0 + 4 * tx] = pk.u;
}

// Exact integral (from -inf to x) of unit hat centered at g.
__device__ __forceinline__ float hat_int(float x, float g) {
    float t = x - (g - 1.0f);
    t = fminf(fmaxf(t, 0.0f), 2.0f);
    float lo = 0.5f * t * t;
    float u  = 2.0f - t;
    float hi = 1.0f - 0.5f * u * u;
    return (t <= 1.0f) ? lo : hi;
}

__device__ __forceinline__ void h4tof(uint2 u, float2& a, float2& b) {
    a = __half22float2(*(__half2*)&u.x);
    b = __half22float2(*(__half2*)&u.y);
}

// ---------------------------------------------------------------------------
// Stage 2: persistent blocks steal (roi, 64-ch chunk) items.
// Half-warp (16 lanes) = one task; lane owns 4 channels (fp16 uint2 loads).
//   Pass A: fixed 5-point unrolled x-contraction, fp32 acc -> fp16 stage.
//   Pass B: y-contraction (fp32), results carried in regs, stored into
//           the stage region re-viewed as fp32 res (pitch 67).
//   Write-out: lanes-over-bins, conflict-free gather, coalesced 49-rows.
// ---------------------------------------------------------------------------
__global__ void __launch_bounds__(256, 8) prroi_pool_kernel(
    const float* __restrict__ rois, float* __restrict__ out)
{
    __shared__ float s_wy[7][MAXW];
    __shared__ float s_wx[7][MAXW];
    __shared__ int   s_jlo[7], s_nj[7];
    __shared__ int   s_ilo[7];
    __shared__ int   s_b, s_j0, s_njr, s_item;
    __shared__ float s_inv;
    extern __shared__ float sm[];
    __half* stage = (__half*)sm;         // [njr*7][64] fp16
    float*  res   = sm;                  // [49][RES_PITCH] fp32, after pass B

    const int tid  = threadIdx.x;
    const int warp = tid >> 5;
    const int lane = tid & 31;
    const int hw   = tid >> 4;             // half-warp id, 0..15
    const int hl   = tid & 15;             // lane within half-warp
    const int cl4  = hl << 2;              // lane's 4 channels (local)

    for (;;) {
        if (tid == 0) s_item = (int)atomicAdd(&g_ctr, 1u);
        __syncthreads();                   // also separates prev write-out
        const int item = s_item;
        if (item >= NITEMS) return;

        const int r     = item >> 2;
        const int chunk = item & 3;
        const float* rp = rois + r * 5;

        // ---- per-bin axis weights + ROI window --------------------------------
        if (tid < 7) {                         // y axis, ph = tid
            float y1 = rp[2] * SCALE, y2 = rp[4] * SCALE;
            float bh = fmaxf(y2 - y1, 0.0f) * (1.0f / 7.0f);
            float ya = y1 + (float)tid * bh;
            float yb = ya + bh;
            int jl = max(0,      (int)ceilf (ya - 1.0f));
            int jh = min(Hf - 1, (int)floorf(yb + 1.0f));
            s_jlo[tid] = jl;
            s_nj[tid]  = min(jh - jl + 1, MAXW);
            #pragma unroll
            for (int m = 0; m < MAXW; ++m) {
                int g = jl + m;
                s_wy[tid][m] = (g <= jh)
                    ? (hat_int(yb, (float)g) - hat_int(ya, (float)g)) : 0.0f;
            }
        } else if (tid >= 32 && tid < 39) {    // x axis, pw = tid-32
            int pw = tid - 32;
            float x1 = rp[1] * SCALE, x2 = rp[3] * SCALE;
            float bw = fmaxf(x2 - x1, 0.0f) * (1.0f / 7.0f);
            float xa = x1 + (float)pw * bw;
            float xb = xa + bw;
            int il = max(0,      (int)ceilf (xa - 1.0f));
            int ih = min(Wf - 1, (int)floorf(xb + 1.0f));
            s_ilo[pw] = il;
            #pragma unroll
            for (int m = 0; m < MAXW; ++m) {
                int g = il + m;
                s_wx[pw][m] = (g <= ih)
                    ? (hat_int(xb, (float)g) - hat_int(xa, (float)g)) : 0.0f;
            }
        } else if (tid == 64) {                // ROI-level y-window + area
            float y1 = rp[2] * SCALE, y2 = rp[4] * SCALE;
            int j0 = max(0,      (int)ceilf (y1 - 1.0f));
            int j1 = min(Hf - 1, (int)floorf(y2 + 1.0f));
            s_j0  = j0;
            s_njr = j1 - j0 + 1;
            s_b   = (int)rp[0];
            float bw = fmaxf(rp[3] - rp[1], 0.0f) * (SCALE / 7.0f);
            float bh = fmaxf(y2 - y1, 0.0f) * (1.0f / 7.0f);
            float area = bw * bh;
            s_inv = (area > 0.0f) ? (1.0f / area) : 0.0f;
        }
        __syncthreads();

        const int j0  = s_j0;
        const int njr = s_njr;
        const __half* fbh = g_featTh
            + (size_t)s_b * (Hf * Wf * Cc) + (chunk << 6) + cl4;

        // ---- Pass A: fixed 5-point unrolled x-contraction ---------------------
        {
            const int tasks = njr * 7;
            int jr, pw;
            if (hw >= 14)      { jr = 2; pw = hw - 14; }
            else if (hw >= 7)  { jr = 1; pw = hw - 7;  }
            else               { jr = 0; pw = hw;      }

            for (int t = hw; t < tasks; t += 16) {
                const float* wxp = s_wx[pw];
                const float w0 = wxp[0], w1 = wxp[1], w2 = wxp[2];
                const float w3 = wxp[3], w4 = wxp[4];
                const __half* p = fbh + ((j0 + jr) * Wf + s_ilo[pw]) * Cc;

                uint2 u0 = __ldg((const uint2*)(p));
                uint2 u1 = __ldg((const uint2*)(p + 256));
                uint2 u2 = __ldg((const uint2*)(p + 512));
                uint2 u3 = __ldg((const uint2*)(p + 768));
                uint2 u4 = __ldg((const uint2*)(p + 1024));

                float2 f0a, f0b, f1a, f1b, f2a, f2b, f3a, f3b, f4a, f4b;
                h4tof(u0, f0a, f0b);
                h4tof(u1, f1a, f1b);
                h4tof(u2, f2a, f2b);
                h4tof(u3, f3a, f3b);
                h4tof(u4, f4a, f4b);

                float4 a;
                a.x = w0 * f0a.x + w1 * f1a.x + w2 * f2a.x + w3 * f3a.x + w4 * f4a.x;
                a.y = w0 * f0a.y + w1 * f1a.y + w2 * f2a.y + w3 * f3a.y + w4 * f4a.y;
                a.z = w0 * f0b.x + w1 * f1b.x + w2 * f2b.x + w3 * f3b.x + w4 * f4b.x;
                a.w = w0 * f0b.y + w1 * f1b.y + w2 * f2b.y + w3 * f3b.y + w4 * f4b.y;

                union { __half2 h[2]; uint2 u; } pk;
                pk.h[0] = __floats2half2_rn(a.x, a.y);
                pk.h[1] = __floats2half2_rn(a.z, a.w);
                *(uint2*)(stage + t * CCH + cl4) = pk.u;

                pw += 2; jr += 2;
                if (pw >= 7) { pw -= 7; ++jr; }
            }
        }
        __syncthreads();

        // ---- Pass B: y-contraction, results carried in registers --------------
        float4 accv[4];
        {
            const float inv = s_inv;
            int ph, pw;
            if (hw >= 14)      { ph = 2; pw = hw - 14; }
            else if (hw >= 7)  { ph = 1; pw = hw - 7;  }
            else               { ph = 0; pw = hw;      }

            #pragma unroll
            for (int k = 0; k < 4; ++k) {
                const int bin = hw + (k << 4);
                if (bin < 49) {
                    const int nj = s_nj[ph];
                    const float* wyp = s_wy[ph];
                    const __half* p = stage + ((s_jlo[ph] - j0) * 7 + pw) * CCH + cl4;

                    float4 acc = make_float4(0.f, 0.f, 0.f, 0.f);
                    for (int j = 0; j < nj; ++j) {
                        const float w = wyp[j];
                        float2 va, vb;
                        h4tof(*(const uint2*)p, va, vb);
                        acc.x += w * va.x; acc.y += w * va.y;
                        acc.z += w * vb.x; acc.w += w * vb.y;
                        p += 7 * CCH;
                    }
                    acc.x *= inv; acc.y *= inv; acc.z *= inv; acc.w *= inv;
                    accv[k] = acc;
                }
                pw += 2; ph += 2;
                if (pw >= 7) { pw -= 7; ++ph; }
            }
        }
        __syncthreads();          // stage reads done; safe to overwrite as res

        #pragma unroll
        for (int k = 0; k < 4; ++k) {
            const int bin = hw + (k << 4);
            if (bin < 49) {
                float* q = res + bin * RES_PITCH + cl4;
                q[0] = accv[k].x;
                q[1] = accv[k].y;
                q[2] = accv[k].z;
                q[3] = accv[k].w;
            }
        }
        __syncthreads();

        // ---- Write-out: lanes over bins, conflict-free gather ------------------
        {
            float* obase = out + ((size_t)r * Cc + (chunk << 6)) * 49;
            for (int cl = warp; cl < CCH; cl += 8) {
                float* o = obase + (size_t)cl * 49;
                o[lane] = res[lane * RES_PITCH + cl];
                if (lane < 17)
                    o[32 + lane] = res[(32 + lane) * RES_PITCH + cl];
            }
        }
    }
}

// ---------------------------------------------------------------------------
extern "C" void kernel_launch(void* const* d_in, const int* in_sizes, int n_in,
                              void* d_out, int out_size) {
    const float* features = (const float*)d_in[0];   // [8,256,48,48]
    const float* rois     = (const float*)d_in[1];   // [300,5]
    float*       out      = (float*)d_out;           // [300,256,7,7]
    (void)in_sizes; (void)n_in; (void)out_size;

    static int configured = 0;
    if (!configured) {
        cudaFuncSetAttribute(prroi_pool_kernel,
                             cudaFuncAttributeMaxDynamicSharedMemorySize,
                             DYN_SMEM);
        configured = 1;
    }

    dim3 tgrid((Hf * Wf) / 32, Cc / 32, Bb);         // (72, 8, 8)
    transpose_kernel<<<tgrid, dim3(8, 32)>>>(features);

    prroi_pool_kernel<<<148 * 8, 256, DYN_SMEM>>>(rois, out);  // persistent
}

// round 17
// speedup vs baseline: 1.1015x; 1.1015x over previous
#include <cuda_runtime.h>
#include <cuda_fp16.h>
#include <math.h>

// Fixed problem shapes
#define Bb 8
#define Cc 256
#define Hf 48
#define Wf 48
#define RR 300
#define SCALE 0.0625f
#define MAXW 5           // grid pts per axis per bin: window span < 5.86 -> <= 5
#define RES_PITCH 67     // odd mod 32 -> conflict-free write-out gather
#define NITEMS (RR * 8)  // (roi, chunk64, bin-half) -> 2400 blocks

// Channels-last fp16 features: [B][H][W][C], zero pad covers fixed-5 over-reads
// (matching weights are exactly 0.0 there).
__device__ __half g_featTh[(size_t)Bb * Hf * Wf * Cc + 4096];

// ---------------------------------------------------------------------------
// Stage 1: transpose [B][C][S] -> fp16 [B][S][C], S = H*W = 2304.
// ---------------------------------------------------------------------------
__global__ void __launch_bounds__(256) transpose_kernel(const float* __restrict__ feat) {
    __shared__ float tile[32][33];     // [c_rel][s_rel]
    const int S = Hf * Wf;
    const int b  = blockIdx.z;
    const int s0 = blockIdx.x * 32;
    const int c0 = blockIdx.y * 32;
    const int tx = threadIdx.x;        // 0..7
    const int ty = threadIdx.y;        // 0..31

    float4 v = *(const float4*)&feat[((size_t)b * Cc + c0 + ty) * S + s0 + 4 * tx];
    tile[ty][4 * tx + 0] = v.x;
    tile[ty][4 * tx + 1] = v.y;
    tile[ty][4 * tx + 2] = v.z;
    tile[ty][4 * tx + 3] = v.w;
    __syncthreads();

    float4 w;
    w.x = tile[4 * tx + 0][ty];
    w.y = tile[4 * tx + 1][ty];
    w.z = tile[4 * tx + 2][ty];
    w.w = tile[4 * tx + 3][ty];
    union { __half2 h[2]; uint2 u; } pk;
    pk.h[0] = __floats2half2_rn(w.x, w.y);
    pk.h[1] = __floats2half2_rn(w.z, w.w);
    *(uint2*)&g_featTh[((size_t)b * S + s0 + ty) * Cc + c0 + 4 * tx] = pk.u;
}

// Exact integral (from -inf to x) of unit hat centered at g.
__device__ __forceinline__ float hat_int(float x, float g) {
    float t = x - (g - 1.0f);
    t = fminf(fmaxf(t, 0.0f), 2.0f);
    float lo = 0.5f * t * t;
    float u  = 2.0f - t;
    float hi = 1.0f - 0.5f * u * u;
    return (t <= 1.0f) ? lo : hi;
}

__device__ __forceinline__ void h4tof(uint2 u, float2& a, float2& b) {
    a = __half22float2(*(__half2*)&u.x);
    b = __half22float2(*(__half2*)&u.y);
}

// ---------------------------------------------------------------------------
// Stage 2: block = (roi, 64-ch chunk, bin-half). Direct per-bin evaluation.
// Half-warp (16 lanes) = one bin; lane owns 4 channels (fp16 uint2 loads).
// Fixed-5 x-unroll (zero-padded wx), dynamic nj <= 5 y-loop. fp32 math.
// Results bounce through smem for coalesced output rows.
// ---------------------------------------------------------------------------
__global__ void __launch_bounds__(256, 6) prroi_pool_kernel(
    const float* __restrict__ rois, float* __restrict__ out)
{
    __shared__ float s_wy[7][MAXW];
    __shared__ float s_wx[7][MAXW];
    __shared__ int   s_jlo[7], s_nj[7];
    __shared__ int   s_ilo[7];
    __shared__ int   s_b;
    __shared__ float s_inv;
    __shared__ float res[25 * RES_PITCH];   // bin-local results

    const int tid  = threadIdx.x;
    const int warp = tid >> 5;
    const int lane = tid & 31;
    const int hw   = tid >> 4;              // half-warp id, 0..15
    const int hl   = tid & 15;              // lane within half-warp
    const int cl4  = hl << 2;               // lane's 4 channels (local)

    const int item  = blockIdx.x;
    const int r     = item >> 3;
    const int chunk = (item >> 1) & 3;
    const int half  = item & 1;
    const int b0    = half ? 25 : 0;
    const int nb    = half ? 24 : 25;

    const float* rp = rois + r * 5;

    // ---- per-bin axis weights + ROI params (14 threads) --------------------
    if (tid < 7) {                         // y axis, ph = tid
        float y1 = rp[2] * SCALE, y2 = rp[4] * SCALE;
        float bh = fmaxf(y2 - y1, 0.0f) * (1.0f / 7.0f);
        float ya = y1 + (float)tid * bh;
        float yb = ya + bh;
        int jl = max(0,      (int)ceilf (ya - 1.0f));
        int jh = min(Hf - 1, (int)floorf(yb + 1.0f));
        s_jlo[tid] = jl;
        s_nj[tid]  = min(jh - jl + 1, MAXW);
        #pragma unroll
        for (int m = 0; m < MAXW; ++m) {
            int g = jl + m;
            s_wy[tid][m] = (g <= jh)
                ? (hat_int(yb, (float)g) - hat_int(ya, (float)g)) : 0.0f;
        }
    } else if (tid >= 32 && tid < 39) {    // x axis, pw = tid-32
        int pw = tid - 32;
        float x1 = rp[1] * SCALE, x2 = rp[3] * SCALE;
        float bw = fmaxf(x2 - x1, 0.0f) * (1.0f / 7.0f);
        float xa = x1 + (float)pw * bw;
        float xb = xa + bw;
        int il = max(0,      (int)ceilf (xa - 1.0f));
        int ih = min(Wf - 1, (int)floorf(xb + 1.0f));
        s_ilo[pw] = il;
        #pragma unroll
        for (int m = 0; m < MAXW; ++m) {
            int g = il + m;
            s_wx[pw][m] = (g <= ih)
                ? (hat_int(xb, (float)g) - hat_int(xa, (float)g)) : 0.0f;
        }
    } else if (tid == 64) {
        float bw = fmaxf(rp[3] - rp[1], 0.0f) * (SCALE / 7.0f);
        float bh = fmaxf(rp[4] - rp[2], 0.0f) * (SCALE / 7.0f);
        float area = bw * bh;
        s_inv = (area > 0.0f) ? (1.0f / area) : 0.0f;
        s_b   = (int)rp[0];
    }
    __syncthreads();

    const float inv = s_inv;
    const __half* fbh = g_featTh
        + (size_t)s_b * (Hf * Wf * Cc) + (chunk << 6) + cl4;

    // ---- direct per-bin evaluation, 2 bins per half-warp --------------------
    #pragma unroll
    for (int k = 0; k < 2; ++k) {
        const int bin_l = hw + (k << 4);
        if (bin_l < nb) {
            const int bin = b0 + bin_l;
            const int ph  = bin / 7;
            const int pw  = bin - ph * 7;
            const int jl  = s_jlo[ph];
            const int nj  = s_nj[ph];
            const float* wyp = s_wy[ph];
            const float* wxp = s_wx[pw];
            const float w0 = wxp[0], w1 = wxp[1], w2 = wxp[2];
            const float w3 = wxp[3], w4 = wxp[4];

            const __half* p = fbh + (jl * Wf + s_ilo[pw]) * Cc;
            float4 acc = make_float4(0.f, 0.f, 0.f, 0.f);

            for (int j = 0; j < nj; ++j) {
                const float wy = wyp[j];
                uint2 u0 = __ldg((const uint2*)(p));
                uint2 u1 = __ldg((const uint2*)(p + 256));
                uint2 u2 = __ldg((const uint2*)(p + 512));
                uint2 u3 = __ldg((const uint2*)(p + 768));
                uint2 u4 = __ldg((const uint2*)(p + 1024));

                float2 f0a, f0b, f1a, f1b, f2a, f2b, f3a, f3b, f4a, f4b;
                h4tof(u0, f0a, f0b);
                h4tof(u1, f1a, f1b);
                h4tof(u2, f2a, f2b);
                h4tof(u3, f3a, f3b);
                h4tof(u4, f4a, f4b);

                float sx, sy, sz, sw;
                sx = w0 * f0a.x + w1 * f1a.x + w2 * f2a.x + w3 * f3a.x + w4 * f4a.x;
                sy = w0 * f0a.y + w1 * f1a.y + w2 * f2a.y + w3 * f3a.y + w4 * f4a.y;
                sz = w0 * f0b.x + w1 * f1b.x + w2 * f2b.x + w3 * f3b.x + w4 * f4b.x;
                sw = w0 * f0b.y + w1 * f1b.y + w2 * f2b.y + w3 * f3b.y + w4 * f4b.y;

                acc.x += wy * sx;
                acc.y += wy * sy;
                acc.z += wy * sz;
                acc.w += wy * sw;
                p += Wf * Cc;
            }

            float* q = res + bin_l * RES_PITCH + cl4;
            q[0] = acc.x * inv;
            q[1] = acc.y * inv;
            q[2] = acc.z * inv;
            q[3] = acc.w * inv;
        }
    }
    __syncthreads();

    // ---- Write-out: lanes over bins, conflict-free gather, coalesced -------
    {
        float* obase = out + ((size_t)r * Cc + (chunk << 6)) * 49 + b0;
        for (int cl = warp; cl < 64; cl += 8) {
            if (lane < nb)
                obase[(size_t)cl * 49 + lane] = res[lane * RES_PITCH + cl];
        }
    }
}

// ---------------------------------------------------------------------------
extern "C" void kernel_launch(void* const* d_in, const int* in_sizes, int n_in,
                              void* d_out, int out_size) {
    const float* features = (const float*)d_in[0];   // [8,256,48,48]
    const float* rois     = (const float*)d_in[1];   // [300,5]
    float*       out      = (float*)d_out;           // [300,256,7,7]
    (void)in_sizes; (void)n_in; (void)out_size;

    dim3 tgrid((Hf * Wf) / 32, Cc / 32, Bb);         // (72, 8, 8)
    transpose_kernel<<<tgrid, dim3(8, 32)>>>(features);

    prroi_pool_kernel<<<NITEMS, 256>>>(rois, out);
}